// round 14
// baseline (speedup 1.0000x reference)
#include <cuda_runtime.h>
#include <cuda_fp16.h>
#include <math.h>

#define GD     17
#define NS     4096
#define DD     768
#define NHH    30
#define CHH    31
#define NCELL  4913      /* 17^3 */
#define FRONT  128
#define SPLITF 4
#define K4_CG  30
#define K4_GRID (K4_CG*2)
#define HH     15        /* h per group */
#define CHK    1024      /* k_A candidate chunk */
#define DTILE  8
#define DPAD   9

/* ---------------- scratch (static device globals: allocation-free) ------- */
__device__ __align__(16) float  g_w[NS][12];
__device__              int    g_cells[NS][3];
__device__              float  g_dist[NS];
__device__              int    g_alive[NS];
__device__              int    g_aliveSamples[NS];
__device__              int    g_nAliveS;
__device__              int    g_cellAlive[NCELL];
__device__              int    g_aliveList[NCELL];
__device__              int    g_nAlive;
__device__              int    g_need;
__device__              float  g_T128[DD];
__device__ __align__(16) float  g_sdp[SPLITF * FRONT * DD];  /* front partials */
__device__ __align__(16) __half g_wgt[NS * DD];              /* fp16 weights */
__device__ __align__(16) float  g_A[NCELL * DD];
__device__ __align__(16) float  g_part[K4_GRID * HH * DD];

/* ---------------- K0: init + per-sample prep ------------------------------ */
__global__ void k_prep(const float* __restrict__ samples,
                       const float* __restrict__ lastp) {
    int n = blockIdx.x * blockDim.x + threadIdx.x;   /* 5120 threads */
    if (n < NCELL) g_cellAlive[n] = 0;
    if (n == 0)    g_need = 0;
    if (n >= NS) return;
    g_alive[n] = 0;

    float s[3] = { samples[3*n], samples[3*n+1], samples[3*n+2] };
    float nx[3];
    if (n < NS - 1) { nx[0]=samples[3*n+3]; nx[1]=samples[3*n+4]; nx[2]=samples[3*n+5]; }
    else            { nx[0]=lastp[0];       nx[1]=lastp[1];       nx[2]=lastp[2]; }
    float e0=s[0]-nx[0], e1=s[1]-nx[1], e2=s[2]-nx[2];
    g_dist[n] = sqrtf(e0*e0 + e1*e1 + e2*e2);

    #pragma unroll
    for (int a = 0; a < 3; a++) {
        float p  = s[a] + 8.0f;
        float f  = floorf(p);
        int  fii = (int)f;
        float dd = p - f;
        int  q   = (a == 0) ? (fii + 1) : (int)ceilf(p);   /* x uses f+1; y,z use ceil */
        int c0 = fii;
        int c1 = min(q, GD - 1);
        int c2 = max(fii - 1, 0);
        int c3 = min(q + 1, GD - 1);
        float mlo = (fii > 0)      ? 1.0f : 0.0f;
        float mhi = (fii + 2 < GD) ? 1.0f : 0.0f;
        float inv = 1.0f / (2.0f + mlo + mhi);
        g_w[n][a*4+0] = (2.0f - dd) * inv;
        g_w[n][a*4+1] = (1.0f + dd) * inv;
        g_w[n][a*4+2] = (1.0f - dd) * mlo * inv;
        g_w[n][a*4+3] = dd * mhi * inv;
        g_cells[n][a] = c0 | (c1 << 8) | (c2 << 16) | (c3 << 24);
    }
}

/* ---------------- K1a: front density partials (split over neighbors) ----- */
__global__ void __launch_bounds__(192) k_density_front(const float* __restrict__ E) {
    __shared__ float2 sco[16];
    __shared__ float  sw[12];
    __shared__ int    sc[3];
    int n  = blockIdx.x;
    int sp = blockIdx.y;
    int t  = threadIdx.x;
    if (t < 12) sw[t] = g_w[n][t];
    if (t < 3)  sc[t] = g_cells[n][t];
    __syncthreads();
    if (t < 16) {
        int m = sp*16 + t;
        int i = m >> 4, j = (m >> 2) & 3, k = m & 3;
        int cx = (sc[0] >> (8*i)) & 255;
        int cy = (sc[1] >> (8*j)) & 255;
        int cz = (sc[2] >> (8*k)) & 255;
        float c = sw[i] * sw[4 + j] * sw[8 + k];
        int off = ((cx*GD + cy)*GD + cz) * (CHH*DD) + NHH*DD;
        sco[t] = make_float2(c, __int_as_float(off));
    }
    __syncthreads();
    int d4 = t * 4;
    const float* Ep = E + d4;
    float ax = 0.f, ay = 0.f, az = 0.f, aw = 0.f;
    #pragma unroll
    for (int m = 0; m < 16; m++) {
        float2 co = sco[m];
        float c = co.x;
        float4 e = __ldg(reinterpret_cast<const float4*>(Ep + __float_as_int(co.y)));
        ax += c * e.x; ay += c * e.y; az += c * e.z; aw += c * e.w;
    }
    float4 o; o.x = ax; o.y = ay; o.z = az; o.w = aw;
    *reinterpret_cast<float4*>(g_sdp + (sp*FRONT + n)*DD + d4) = o;
}

/* ------ K2a: fused combine + scan, coalesced via smem tile ---------------- */
__global__ void __launch_bounds__(256) k_wgt_front() {
    __shared__ float  ssd[FRONT * DPAD];     /* 128 x 9 fp32, pad vs bank conflict */
    __shared__ __half swgt[FRONT * DTILE];   /* 128 x 8 fp16 staged output */
    int t  = threadIdx.x;
    int d0 = blockIdx.x * DTILE;             /* 96 blocks x 8 channels */

    /* phase 1: coalesced load of 4 partials, combine, relu, *dist -> smem */
    #pragma unroll
    for (int it = 0; it < 4; it++) {
        int idx = it*256 + t;                /* 1024 = 128n x 8d */
        int n = idx >> 3, dl = idx & 7;
        int g = n*DD + d0 + dl;
        float v = ((g_sdp[g] + g_sdp[FRONT*DD + g])
                 + (g_sdp[2*FRONT*DD + g] + g_sdp[3*FRONT*DD + g]));
        ssd[n*DPAD + dl] = fmaxf(v, 0.0f) * g_dist[n];
    }
    __syncthreads();

    /* phase 2: warp w scans channel d0+w over n (reads from smem) */
    int w = t >> 5, lane = t & 31;
    int n0 = lane * 4;
    float s0 = ssd[(n0+0)*DPAD + w];
    float s1 = ssd[(n0+1)*DPAD + w];
    float s2 = ssd[(n0+2)*DPAD + w];
    float s3 = ssd[(n0+3)*DPAD + w];
    float i0 = s0, i1 = i0 + s1, i2 = i1 + s2, i3 = i2 + s3;
    float run = i3;
    #pragma unroll
    for (int off = 1; off < 32; off <<= 1) {
        float x = __shfl_up_sync(0xffffffffu, run, off);
        if (lane >= off) run += x;
    }
    float ebase = run - i3;
    float in0 = ebase + i0, in1 = ebase + i1, in2 = ebase + i2, in3 = ebase + i3;
    float t0 = __expf(-ebase), t1 = __expf(-in0), t2 = __expf(-in1), t3 = __expf(-in2);
    float t4 = __expf(-in3);
    __half h0 = __float2half(t0 - t1);
    __half h1 = __float2half(t1 - t2);
    __half h2 = __float2half(t2 - t3);
    __half h3 = __float2half(t3 - t4);
    swgt[(n0+0)*DTILE + w] = h0;
    swgt[(n0+1)*DTILE + w] = h1;
    swgt[(n0+2)*DTILE + w] = h2;
    swgt[(n0+3)*DTILE + w] = h3;
    if (__half_as_ushort(h0) != 0) g_alive[n0+0] = 1;
    if (__half_as_ushort(h1) != 0) g_alive[n0+1] = 1;
    if (__half_as_ushort(h2) != 0) g_alive[n0+2] = 1;
    if (__half_as_ushort(h3) != 0) g_alive[n0+3] = 1;
    if (lane == 31) {
        g_T128[d0 + w] = t4;
        /* safe-skip: all future wgt < T <= 2^-25 rounds to fp16 +0 */
        if (t4 > 0x1p-25f) atomicOr(&g_need, 1);
    }
    __syncthreads();

    /* phase 3: coalesced store of staged wgt */
    #pragma unroll
    for (int it = 0; it < 4; it++) {
        int idx = it*256 + t;
        int n = idx >> 3, dl = idx & 7;
        g_wgt[n*DD + d0 + dl] = swgt[n*DTILE + dl];
    }
}

/* ------ K-rest: guarded fallback (density + scan fused, tiny grid) -------- */
__global__ void __launch_bounds__(96) k_rest(const float* __restrict__ E) {
    if (!g_need) return;
    __shared__ float2 sco[64];
    int t = threadIdx.x;
    int d = blockIdx.x * 96 + t;            /* 8 blocks x 96 = 768 channels */
    float T = g_T128[d];
    for (int n = FRONT; n < NS; n++) {
        __syncthreads();
        if (t < 64) {
            int i = t >> 4, j = (t >> 2) & 3, k = t & 3;
            int cx = (g_cells[n][0] >> (8*i)) & 255;
            int cy = (g_cells[n][1] >> (8*j)) & 255;
            int cz = (g_cells[n][2] >> (8*k)) & 255;
            float c = g_w[n][i] * g_w[n][4 + j] * g_w[n][8 + k];
            int off = ((cx*GD + cy)*GD + cz) * (CHH*DD) + NHH*DD;
            sco[t] = make_float2(c, __int_as_float(off));
        }
        __syncthreads();
        float dens = 0.f;
        #pragma unroll 4
        for (int m = 0; m < 64; m++) {
            float2 co = sco[m];
            dens += co.x * __ldg(E + __float_as_int(co.y) + d);
        }
        float sd = fmaxf(dens, 0.0f) * g_dist[n];
        float e  = __expf(-sd);
        __half hv = __float2half(T * (1.0f - e));
        g_wgt[n*DD + d] = hv;
        if (__half_as_ushort(hv) != 0) g_alive[n] = 1;
        T *= e;
    }
}

/* ---------------- K-lists: alive samples -> mark cells -> alive cells ----- */
__global__ void k_lists() {
    __shared__ int wsum[32];
    __shared__ int s_ns;
    int t = threadIdx.x;                   /* 1024 threads */
    int lane = t & 31, wid = t >> 5;

    /* phase A: ordered alive-sample list */
    {
        int vals[4]; int s = 0;
        #pragma unroll
        for (int k = 0; k < 4; k++) { int v = g_alive[t*4 + k]; vals[k] = v; s += v; }
        int inc = s;
        #pragma unroll
        for (int off = 1; off < 32; off <<= 1) {
            int x = __shfl_up_sync(0xffffffffu, inc, off);
            if (lane >= off) inc += x;
        }
        if (lane == 31) wsum[wid] = inc;
        __syncthreads();
        if (wid == 0) {
            int v = wsum[lane];
            #pragma unroll
            for (int off = 1; off < 32; off <<= 1) {
                int x = __shfl_up_sync(0xffffffffu, v, off);
                if (lane >= off) v += x;
            }
            wsum[lane] = v;
        }
        __syncthreads();
        int base = inc - s + ((wid > 0) ? wsum[wid-1] : 0);
        #pragma unroll
        for (int k = 0; k < 4; k++)
            if (vals[k]) g_aliveSamples[base++] = t*4 + k;
        if (t == 0) { s_ns = wsum[31]; g_nAliveS = wsum[31]; }
    }
    __syncthreads();

    /* phase B: mark cells touched by alive samples */
    int ns = s_ns;
    for (int w = t; w < ns * 64; w += 1024) {
        int i = w >> 6, u = w & 63;
        int n = g_aliveSamples[i];
        int iu = u >> 4, ju = (u >> 2) & 3, ku = u & 3;
        int cx = (g_cells[n][0] >> (8*iu)) & 255;
        int cy = (g_cells[n][1] >> (8*ju)) & 255;
        int cz = (g_cells[n][2] >> (8*ku)) & 255;
        g_cellAlive[(cx*GD + cy)*GD + cz] = 1;
    }
    __syncthreads();

    /* phase C: ordered alive-cell list */
    {
        int vals[5]; int s = 0;
        #pragma unroll
        for (int k = 0; k < 5; k++) {
            int idx = t*5 + k;
            int v = (idx < NCELL) ? g_cellAlive[idx] : 0;
            vals[k] = v; s += v;
        }
        int inc = s;
        #pragma unroll
        for (int off = 1; off < 32; off <<= 1) {
            int x = __shfl_up_sync(0xffffffffu, inc, off);
            if (lane >= off) inc += x;
        }
        if (lane == 31) wsum[wid] = inc;
        __syncthreads();
        if (wid == 0) {
            int v = wsum[lane];
            #pragma unroll
            for (int off = 1; off < 32; off <<= 1) {
                int x = __shfl_up_sync(0xffffffffu, v, off);
                if (lane >= off) v += x;
            }
            wsum[lane] = v;
        }
        __syncthreads();
        int base = inc - s + ((wid > 0) ? wsum[wid-1] : 0);
        #pragma unroll
        for (int k = 0; k < 5; k++) {
            int idx = t*5 + k;
            if (idx < NCELL && vals[k]) g_aliveList[base++] = idx;
        }
        if (t == 0) g_nAlive = wsum[31];
    }
}

/* ---------------- K3: A[c,d] over alive cells x alive samples ------------- */
__global__ void __launch_bounds__(192) k_A() {
    __shared__ float2 scand[CHK];          /* (coef, byte-off as int) */
    int bi = blockIdx.x;
    if (bi >= g_nAlive) return;
    int c = g_aliveList[bi];
    int iz = c % GD; int r = c / GD; int iy = r % GD; int ix = r / GD;
    int t = threadIdx.x;
    int ns = g_nAliveS;
    int d4 = t * 4;
    const __half* Wp = g_wgt + d4;
    float ax = 0.f, ay = 0.f, az = 0.f, aw = 0.f;

    for (int base = 0; base < ns; base += CHK) {
        int m = min(CHK, ns - base);
        __syncthreads();
        for (int j = t; j < m; j += 192) {
            int n = g_aliveSamples[base + j];
            int cpx = g_cells[n][0], cpy = g_cells[n][1], cpz = g_cells[n][2];
            float wx = 0.f, wy = 0.f, wz = 0.f;
            #pragma unroll
            for (int u = 0; u < 4; u++) {
                if (((cpx >> (8*u)) & 255) == ix) wx += g_w[n][u];
                if (((cpy >> (8*u)) & 255) == iy) wy += g_w[n][4 + u];
                if (((cpz >> (8*u)) & 255) == iz) wz += g_w[n][8 + u];
            }
            scand[j] = make_float2(wx * wy * wz, __int_as_float(n * DD));
        }
        __syncthreads();
        for (int j = 0; j < m; j++) {
            float2 ca = scand[j];
            float cf = ca.x;
            if (cf != 0.0f) {
                uint2 u = *reinterpret_cast<const uint2*>(Wp + __float_as_int(ca.y));
                float2 f0 = __half22float2(*reinterpret_cast<const __half2*>(&u.x));
                float2 f1 = __half22float2(*reinterpret_cast<const __half2*>(&u.y));
                ax += cf * f0.x; ay += cf * f0.y; az += cf * f1.x; aw += cf * f1.y;
            }
        }
    }
    float4 o; o.x = ax; o.y = ay; o.z = az; o.w = aw;
    *reinterpret_cast<float4*>(g_A + c*DD + d4) = o;
}

/* ---------------- K4: out partials over compacted alive cells ------------- */
__global__ void __launch_bounds__(192, 2) k_out(const float* __restrict__ E) {
    int cg = blockIdx.x >> 1;
    int hg = blockIdx.x & 1;
    int t = threadIdx.x;
    int d4 = t * 4;
    float4 acc[HH];
    #pragma unroll
    for (int h = 0; h < HH; h++) { acc[h].x=0.f; acc[h].y=0.f; acc[h].z=0.f; acc[h].w=0.f; }

    int na = g_nAlive;
    for (int i = cg; i < na; i += K4_CG) {
        int c = g_aliveList[i];
        float4 a = *reinterpret_cast<const float4*>(g_A + c*DD + d4);
        const float4* base = reinterpret_cast<const float4*>(E + c*(CHH*DD) + hg*HH*DD + d4);
        #pragma unroll
        for (int h = 0; h < HH; h++) {
            float4 e = __ldcs(base + h*(DD/4));
            acc[h].x += a.x * e.x;
            acc[h].y += a.y * e.y;
            acc[h].z += a.z * e.z;
            acc[h].w += a.w * e.w;
        }
    }
    float* pb = g_part + blockIdx.x * (HH*DD);
    #pragma unroll
    for (int h = 0; h < HH; h++)
        *reinterpret_cast<float4*>(pb + h*DD + d4) = acc[h];
}

/* ---------------- K5: reduce partials -> d_out ---------------------------- */
__global__ void k_reduce(float* __restrict__ out) {
    int idx = blockIdx.x * blockDim.x + threadIdx.x;   /* 5760 threads */
    if (idx >= (NHH * DD) / 4) return;
    int h  = idx / (DD/4);
    int d4 = (idx - h*(DD/4)) * 4;
    int g  = h / HH;
    int hh = h - g*HH;
    float ax=0.f, ay=0.f, az=0.f, aw=0.f;
    #pragma unroll 5
    for (int cg = 0; cg < K4_CG; cg++) {
        const float4 v = *reinterpret_cast<const float4*>(
            g_part + (cg*2 + g) * (HH*DD) + hh*DD + d4);
        ax += v.x; ay += v.y; az += v.z; aw += v.w;
    }
    float4 o; o.x=ax; o.y=ay; o.z=az; o.w=aw;
    *reinterpret_cast<float4*>(out + h*DD + d4) = o;
}

/* ---------------- launcher ------------------------------------------------ */
extern "C" void kernel_launch(void* const* d_in, const int* in_sizes, int n_in,
                              void* d_out, int out_size) {
    const float* samples = (const float*)d_in[0];
    const float* lastp   = (const float*)d_in[1];
    const float* E       = (const float*)d_in[2];
    for (int i = 0; i < n_in; i++) {
        if (in_sizes[i] == NS * 3)            samples = (const float*)d_in[i];
        else if (in_sizes[i] == 3)            lastp   = (const float*)d_in[i];
        else if (in_sizes[i] > 1000000)       E       = (const float*)d_in[i];
    }

    k_prep          <<<(NCELL + 255)/256, 256>>>(samples, lastp);
    k_density_front <<<dim3(FRONT, SPLITF), 192>>>(E);
    k_wgt_front     <<<96, 256>>>();
    k_rest          <<<8, 96>>>(E);
    k_lists         <<<1, 1024>>>();
    k_A             <<<NCELL, 192>>>();
    k_out           <<<K4_GRID, 192>>>(E);
    k_reduce        <<<30, 192>>>((float*)d_out);
    (void)out_size;
}

// round 15
// speedup vs baseline: 1.4504x; 1.4504x over previous
#include <cuda_runtime.h>
#include <cuda_fp16.h>
#include <math.h>

#define GD     17
#define NS     4096
#define DD     768
#define NHH    30
#define CHH    31
#define NCELL  4913      /* 17^3 */
#define FRONT  128
#define SPLITF 4
#define K4_CG  74
#define K4_GRID (K4_CG*2)
#define HH     15        /* h per group */
#define CHK    1024      /* k_A candidate chunk */
#define DTILE  8
#define DPAD   9

/* ---------------- scratch (static device globals: allocation-free) ------- */
__device__ __align__(16) float  g_w[NS][12];
__device__              int    g_cells[NS][3];
__device__              float  g_dist[NS];
__device__              int    g_alive[NS];
__device__              int    g_aliveSamples[NS];
__device__              int    g_nAliveS;
__device__              int    g_cellAlive[NCELL];
__device__              int    g_aliveList[NCELL];
__device__              int    g_nAlive;
__device__              int    g_need;
__device__              float  g_T128[DD];
__device__ __align__(16) float  g_sdp[SPLITF * FRONT * DD];  /* front partials */
__device__ __align__(16) __half g_wgt[NS * DD];              /* fp16 weights */
__device__ __align__(16) float  g_A[NCELL * DD];
__device__ __align__(16) float  g_part[K4_GRID * HH * DD];

/* ---------------- K0: init + per-sample prep ------------------------------ */
__global__ void k_prep(const float* __restrict__ samples,
                       const float* __restrict__ lastp) {
    int n = blockIdx.x * blockDim.x + threadIdx.x;   /* 5120 threads */
    if (n < NCELL) g_cellAlive[n] = 0;
    if (n == 0)    g_need = 0;
    if (n >= NS) return;
    g_alive[n] = 0;

    float s[3] = { samples[3*n], samples[3*n+1], samples[3*n+2] };
    float nx[3];
    if (n < NS - 1) { nx[0]=samples[3*n+3]; nx[1]=samples[3*n+4]; nx[2]=samples[3*n+5]; }
    else            { nx[0]=lastp[0];       nx[1]=lastp[1];       nx[2]=lastp[2]; }
    float e0=s[0]-nx[0], e1=s[1]-nx[1], e2=s[2]-nx[2];
    g_dist[n] = sqrtf(e0*e0 + e1*e1 + e2*e2);

    #pragma unroll
    for (int a = 0; a < 3; a++) {
        float p  = s[a] + 8.0f;
        float f  = floorf(p);
        int  fii = (int)f;
        float dd = p - f;
        int  q   = (a == 0) ? (fii + 1) : (int)ceilf(p);   /* x uses f+1; y,z use ceil */
        int c0 = fii;
        int c1 = min(q, GD - 1);
        int c2 = max(fii - 1, 0);
        int c3 = min(q + 1, GD - 1);
        float mlo = (fii > 0)      ? 1.0f : 0.0f;
        float mhi = (fii + 2 < GD) ? 1.0f : 0.0f;
        float inv = 1.0f / (2.0f + mlo + mhi);
        g_w[n][a*4+0] = (2.0f - dd) * inv;
        g_w[n][a*4+1] = (1.0f + dd) * inv;
        g_w[n][a*4+2] = (1.0f - dd) * mlo * inv;
        g_w[n][a*4+3] = dd * mhi * inv;
        g_cells[n][a] = c0 | (c1 << 8) | (c2 << 16) | (c3 << 24);
    }
}

/* ---------------- K1a: front density partials (split over neighbors) ----- */
__global__ void __launch_bounds__(192) k_density_front(const float* __restrict__ E) {
    __shared__ float2 sco[16];
    __shared__ float  sw[12];
    __shared__ int    sc[3];
    int n  = blockIdx.x;
    int sp = blockIdx.y;
    int t  = threadIdx.x;
    if (t < 12) sw[t] = g_w[n][t];
    if (t < 3)  sc[t] = g_cells[n][t];
    __syncthreads();
    if (t < 16) {
        int m = sp*16 + t;
        int i = m >> 4, j = (m >> 2) & 3, k = m & 3;
        int cx = (sc[0] >> (8*i)) & 255;
        int cy = (sc[1] >> (8*j)) & 255;
        int cz = (sc[2] >> (8*k)) & 255;
        float c = sw[i] * sw[4 + j] * sw[8 + k];
        int off = ((cx*GD + cy)*GD + cz) * (CHH*DD) + NHH*DD;
        sco[t] = make_float2(c, __int_as_float(off));
    }
    __syncthreads();
    int d4 = t * 4;
    const float* Ep = E + d4;
    float ax = 0.f, ay = 0.f, az = 0.f, aw = 0.f;
    #pragma unroll
    for (int m = 0; m < 16; m++) {
        float2 co = sco[m];
        float c = co.x;
        float4 e = __ldg(reinterpret_cast<const float4*>(Ep + __float_as_int(co.y)));
        ax += c * e.x; ay += c * e.y; az += c * e.z; aw += c * e.w;
    }
    float4 o; o.x = ax; o.y = ay; o.z = az; o.w = aw;
    *reinterpret_cast<float4*>(g_sdp + (sp*FRONT + n)*DD + d4) = o;
}

/* ------ K2a: fused combine + scan, coalesced via smem tile ---------------- */
__global__ void __launch_bounds__(256) k_wgt_front() {
    __shared__ float  ssd[FRONT * DPAD];     /* 128 x 9 fp32, pad vs bank conflict */
    __shared__ __half swgt[FRONT * DTILE];   /* 128 x 8 fp16 staged output */
    int t  = threadIdx.x;
    int d0 = blockIdx.x * DTILE;             /* 96 blocks x 8 channels */

    /* phase 1: coalesced load of 4 partials, combine, relu, *dist -> smem */
    #pragma unroll
    for (int it = 0; it < 4; it++) {
        int idx = it*256 + t;                /* 1024 = 128n x 8d */
        int n = idx >> 3, dl = idx & 7;
        int g = n*DD + d0 + dl;
        float v = ((g_sdp[g] + g_sdp[FRONT*DD + g])
                 + (g_sdp[2*FRONT*DD + g] + g_sdp[3*FRONT*DD + g]));
        ssd[n*DPAD + dl] = fmaxf(v, 0.0f) * g_dist[n];
    }
    __syncthreads();

    /* phase 2: warp w scans channel d0+w over n (reads from smem) */
    int w = t >> 5, lane = t & 31;
    int n0 = lane * 4;
    float s0 = ssd[(n0+0)*DPAD + w];
    float s1 = ssd[(n0+1)*DPAD + w];
    float s2 = ssd[(n0+2)*DPAD + w];
    float s3 = ssd[(n0+3)*DPAD + w];
    float i0 = s0, i1 = i0 + s1, i2 = i1 + s2, i3 = i2 + s3;
    float run = i3;
    #pragma unroll
    for (int off = 1; off < 32; off <<= 1) {
        float x = __shfl_up_sync(0xffffffffu, run, off);
        if (lane >= off) run += x;
    }
    float ebase = run - i3;
    float in0 = ebase + i0, in1 = ebase + i1, in2 = ebase + i2, in3 = ebase + i3;
    float t0 = __expf(-ebase), t1 = __expf(-in0), t2 = __expf(-in1), t3 = __expf(-in2);
    float t4 = __expf(-in3);
    __half h0 = __float2half(t0 - t1);
    __half h1 = __float2half(t1 - t2);
    __half h2 = __float2half(t2 - t3);
    __half h3 = __float2half(t3 - t4);
    swgt[(n0+0)*DTILE + w] = h0;
    swgt[(n0+1)*DTILE + w] = h1;
    swgt[(n0+2)*DTILE + w] = h2;
    swgt[(n0+3)*DTILE + w] = h3;
    if (__half_as_ushort(h0) != 0) g_alive[n0+0] = 1;
    if (__half_as_ushort(h1) != 0) g_alive[n0+1] = 1;
    if (__half_as_ushort(h2) != 0) g_alive[n0+2] = 1;
    if (__half_as_ushort(h3) != 0) g_alive[n0+3] = 1;
    if (lane == 31) {
        g_T128[d0 + w] = t4;
        /* safe-skip: all future wgt < T <= 2^-25 rounds to fp16 +0 */
        if (t4 > 0x1p-25f) atomicOr(&g_need, 1);
    }
    __syncthreads();

    /* phase 3: coalesced store of staged wgt */
    #pragma unroll
    for (int it = 0; it < 4; it++) {
        int idx = it*256 + t;
        int n = idx >> 3, dl = idx & 7;
        g_wgt[n*DD + d0 + dl] = swgt[n*DTILE + dl];
    }
}

/* ------ K-rest: guarded fallback (density + scan fused, tiny grid) -------- */
__global__ void __launch_bounds__(96) k_rest(const float* __restrict__ E) {
    if (!g_need) return;
    __shared__ float2 sco[64];
    int t = threadIdx.x;
    int d = blockIdx.x * 96 + t;            /* 8 blocks x 96 = 768 channels */
    float T = g_T128[d];
    for (int n = FRONT; n < NS; n++) {
        __syncthreads();
        if (t < 64) {
            int i = t >> 4, j = (t >> 2) & 3, k = t & 3;
            int cx = (g_cells[n][0] >> (8*i)) & 255;
            int cy = (g_cells[n][1] >> (8*j)) & 255;
            int cz = (g_cells[n][2] >> (8*k)) & 255;
            float c = g_w[n][i] * g_w[n][4 + j] * g_w[n][8 + k];
            int off = ((cx*GD + cy)*GD + cz) * (CHH*DD) + NHH*DD;
            sco[t] = make_float2(c, __int_as_float(off));
        }
        __syncthreads();
        float dens = 0.f;
        #pragma unroll 4
        for (int m = 0; m < 64; m++) {
            float2 co = sco[m];
            dens += co.x * __ldg(E + __float_as_int(co.y) + d);
        }
        float sd = fmaxf(dens, 0.0f) * g_dist[n];
        float e  = __expf(-sd);
        __half hv = __float2half(T * (1.0f - e));
        g_wgt[n*DD + d] = hv;
        if (__half_as_ushort(hv) != 0) g_alive[n] = 1;
        T *= e;
    }
}

/* ---------------- K-lists: alive samples -> mark cells -> alive cells ----- */
__global__ void k_lists() {
    __shared__ int wsum[32];
    __shared__ int s_ns;
    int t = threadIdx.x;                   /* 1024 threads */
    int lane = t & 31, wid = t >> 5;

    /* phase A: ordered alive-sample list */
    {
        int vals[4]; int s = 0;
        #pragma unroll
        for (int k = 0; k < 4; k++) { int v = g_alive[t*4 + k]; vals[k] = v; s += v; }
        int inc = s;
        #pragma unroll
        for (int off = 1; off < 32; off <<= 1) {
            int x = __shfl_up_sync(0xffffffffu, inc, off);
            if (lane >= off) inc += x;
        }
        if (lane == 31) wsum[wid] = inc;
        __syncthreads();
        if (wid == 0) {
            int v = wsum[lane];
            #pragma unroll
            for (int off = 1; off < 32; off <<= 1) {
                int x = __shfl_up_sync(0xffffffffu, v, off);
                if (lane >= off) v += x;
            }
            wsum[lane] = v;
        }
        __syncthreads();
        int base = inc - s + ((wid > 0) ? wsum[wid-1] : 0);
        #pragma unroll
        for (int k = 0; k < 4; k++)
            if (vals[k]) g_aliveSamples[base++] = t*4 + k;
        if (t == 0) { s_ns = wsum[31]; g_nAliveS = wsum[31]; }
    }
    __syncthreads();

    /* phase B: mark cells touched by alive samples */
    int ns = s_ns;
    for (int w = t; w < ns * 64; w += 1024) {
        int i = w >> 6, u = w & 63;
        int n = g_aliveSamples[i];
        int iu = u >> 4, ju = (u >> 2) & 3, ku = u & 3;
        int cx = (g_cells[n][0] >> (8*iu)) & 255;
        int cy = (g_cells[n][1] >> (8*ju)) & 255;
        int cz = (g_cells[n][2] >> (8*ku)) & 255;
        g_cellAlive[(cx*GD + cy)*GD + cz] = 1;
    }
    __syncthreads();

    /* phase C: ordered alive-cell list */
    {
        int vals[5]; int s = 0;
        #pragma unroll
        for (int k = 0; k < 5; k++) {
            int idx = t*5 + k;
            int v = (idx < NCELL) ? g_cellAlive[idx] : 0;
            vals[k] = v; s += v;
        }
        int inc = s;
        #pragma unroll
        for (int off = 1; off < 32; off <<= 1) {
            int x = __shfl_up_sync(0xffffffffu, inc, off);
            if (lane >= off) inc += x;
        }
        if (lane == 31) wsum[wid] = inc;
        __syncthreads();
        if (wid == 0) {
            int v = wsum[lane];
            #pragma unroll
            for (int off = 1; off < 32; off <<= 1) {
                int x = __shfl_up_sync(0xffffffffu, v, off);
                if (lane >= off) v += x;
            }
            wsum[lane] = v;
        }
        __syncthreads();
        int base = inc - s + ((wid > 0) ? wsum[wid-1] : 0);
        #pragma unroll
        for (int k = 0; k < 5; k++) {
            int idx = t*5 + k;
            if (idx < NCELL && vals[k]) g_aliveList[base++] = idx;
        }
        if (t == 0) g_nAlive = wsum[31];
    }
}

/* ---------------- K3: A[c,d] over alive cells x alive samples ------------- */
__global__ void __launch_bounds__(192) k_A() {
    __shared__ float2 scand[CHK];          /* (coef, byte-off as int) */
    int bi = blockIdx.x;
    if (bi >= g_nAlive) return;
    int c = g_aliveList[bi];
    int iz = c % GD; int r = c / GD; int iy = r % GD; int ix = r / GD;
    int t = threadIdx.x;
    int ns = g_nAliveS;
    int d4 = t * 4;
    const __half* Wp = g_wgt + d4;
    float ax = 0.f, ay = 0.f, az = 0.f, aw = 0.f;

    for (int base = 0; base < ns; base += CHK) {
        int m = min(CHK, ns - base);
        __syncthreads();
        for (int j = t; j < m; j += 192) {
            int n = g_aliveSamples[base + j];
            int cpx = g_cells[n][0], cpy = g_cells[n][1], cpz = g_cells[n][2];
            float wx = 0.f, wy = 0.f, wz = 0.f;
            #pragma unroll
            for (int u = 0; u < 4; u++) {
                if (((cpx >> (8*u)) & 255) == ix) wx += g_w[n][u];
                if (((cpy >> (8*u)) & 255) == iy) wy += g_w[n][4 + u];
                if (((cpz >> (8*u)) & 255) == iz) wz += g_w[n][8 + u];
            }
            scand[j] = make_float2(wx * wy * wz, __int_as_float(n * DD));
        }
        __syncthreads();
        for (int j = 0; j < m; j++) {
            float2 ca = scand[j];
            float cf = ca.x;
            if (cf != 0.0f) {
                uint2 u = *reinterpret_cast<const uint2*>(Wp + __float_as_int(ca.y));
                float2 f0 = __half22float2(*reinterpret_cast<const __half2*>(&u.x));
                float2 f1 = __half22float2(*reinterpret_cast<const __half2*>(&u.y));
                ax += cf * f0.x; ay += cf * f0.y; az += cf * f1.x; aw += cf * f1.y;
            }
        }
    }
    float4 o; o.x = ax; o.y = ay; o.z = az; o.w = aw;
    *reinterpret_cast<float4*>(g_A + c*DD + d4) = o;
}

/* ---------------- K4: out partials over compacted alive cells ------------- */
__global__ void __launch_bounds__(192, 2) k_out(const float* __restrict__ E) {
    int cg = blockIdx.x >> 1;
    int hg = blockIdx.x & 1;
    int t = threadIdx.x;
    int d4 = t * 4;
    float4 acc[HH];
    #pragma unroll
    for (int h = 0; h < HH; h++) { acc[h].x=0.f; acc[h].y=0.f; acc[h].z=0.f; acc[h].w=0.f; }

    int na = g_nAlive;
    for (int i = cg; i < na; i += K4_CG) {
        int c = g_aliveList[i];
        float4 a = *reinterpret_cast<const float4*>(g_A + c*DD + d4);
        const float4* base = reinterpret_cast<const float4*>(E + c*(CHH*DD) + hg*HH*DD + d4);
        #pragma unroll
        for (int h = 0; h < HH; h++) {
            float4 e = __ldcs(base + h*(DD/4));
            acc[h].x += a.x * e.x;
            acc[h].y += a.y * e.y;
            acc[h].z += a.z * e.z;
            acc[h].w += a.w * e.w;
        }
    }
    float* pb = g_part + blockIdx.x * (HH*DD);
    #pragma unroll
    for (int h = 0; h < HH; h++)
        *reinterpret_cast<float4*>(pb + h*DD + d4) = acc[h];
}

/* ---------------- K5: reduce partials -> d_out ---------------------------- */
__global__ void k_reduce(float* __restrict__ out) {
    int idx = blockIdx.x * blockDim.x + threadIdx.x;   /* 5760 threads */
    if (idx >= (NHH * DD) / 4) return;
    int h  = idx / (DD/4);
    int d4 = (idx - h*(DD/4)) * 4;
    int g  = h / HH;
    int hh = h - g*HH;
    float ax=0.f, ay=0.f, az=0.f, aw=0.f;
    #pragma unroll 4
    for (int cg = 0; cg < K4_CG; cg++) {
        const float4 v = *reinterpret_cast<const float4*>(
            g_part + (cg*2 + g) * (HH*DD) + hh*DD + d4);
        ax += v.x; ay += v.y; az += v.z; aw += v.w;
    }
    float4 o; o.x=ax; o.y=ay; o.z=az; o.w=aw;
    *reinterpret_cast<float4*>(out + h*DD + d4) = o;
}

/* ---------------- launcher ------------------------------------------------ */
extern "C" void kernel_launch(void* const* d_in, const int* in_sizes, int n_in,
                              void* d_out, int out_size) {
    const float* samples = (const float*)d_in[0];
    const float* lastp   = (const float*)d_in[1];
    const float* E       = (const float*)d_in[2];
    for (int i = 0; i < n_in; i++) {
        if (in_sizes[i] == NS * 3)            samples = (const float*)d_in[i];
        else if (in_sizes[i] == 3)            lastp   = (const float*)d_in[i];
        else if (in_sizes[i] > 1000000)       E       = (const float*)d_in[i];
    }

    k_prep          <<<(NCELL + 255)/256, 256>>>(samples, lastp);
    k_density_front <<<dim3(FRONT, SPLITF), 192>>>(E);
    k_wgt_front     <<<96, 256>>>();
    k_rest          <<<8, 96>>>(E);
    k_lists         <<<1, 1024>>>();
    k_A             <<<NCELL, 192>>>();
    k_out           <<<K4_GRID, 192>>>(E);
    k_reduce        <<<30, 192>>>((float*)d_out);
    (void)out_size;
}